// round 7
// baseline (speedup 1.0000x reference)
#include <cuda_runtime.h>
#include <cuda_fp16.h>
#include <cstdint>

// Problem constants
#define T_STEPS 512
#define BATCH   256
#define DIN     128
#define HID     512
#define KTOT    640          // DIN + HID

// Tiling
#define P_B 8                // batch groups
#define P_N 16               // n-slices per group
#define B_TILE 32            // batch rows per CTA (M)
#define N_SLICE 32           // H columns per CTA
#define KC 128               // K chunk (halves) per z slot
#define NCHUNK 5             // 640 / 128
#define NKG 8                // kg16 groups per chunk
#define KGG_TOT 40           // 640 / 16
#define NTHREADS 512
#define GRID (P_B * P_N)

// Shared memory layout (uint32 units)
#define OFF_WF  0            // B frag staging: 40 kg * 4 ntp * 32 lane * 4 = 20480 u32 (80KB)
#define OFF_Z   20480        // 5 chunk slots * 2048 u32 (each 32 rows x 128 halves = 8KB)
#define OFF_EPI 30720        // 4 wk-buffers * 32*66 = 8448
#define OFF_BC  39168        // 32
#define OFF_BT  39200        // 32
#define SMEM_U32 39232
#define SMEM_BYTES (SMEM_U32 * 4)   // 156928 B

#define ZBUF_BYTES 8192

// Persistent device state.
// g_hz: hidden state as fp16, PRE-SWIZZLED in the smem fragment byte layout.
__device__ __align__(16) char g_hz[2][P_B][4][ZBUF_BYTES];
__device__ float    g_ypart[2][BATCH][P_N];
__device__ unsigned g_flag[P_B][P_N];   // monotonic step counters (reset at kernel end)
__device__ unsigned g_exit[P_B];        // exit barrier for flag reset

__device__ __forceinline__ void mma_f16(float* c, unsigned a0, unsigned a1,
                                        unsigned a2, unsigned a3,
                                        unsigned b0, unsigned b1) {
    asm("mma.sync.aligned.m16n8k16.row.col.f32.f16.f16.f32 "
        "{%0,%1,%2,%3},{%4,%5,%6,%7},{%8,%9},{%0,%1,%2,%3};"
        : "+f"(c[0]), "+f"(c[1]), "+f"(c[2]), "+f"(c[3])
        : "r"(a0), "r"(a1), "r"(a2), "r"(a3), "r"(b0), "r"(b1));
}

__device__ __forceinline__ void ldsm_x4(unsigned& a0, unsigned& a1,
                                        unsigned& a2, unsigned& a3, unsigned saddr) {
    asm volatile("ldmatrix.sync.aligned.m8n8.x4.shared.b16 {%0,%1,%2,%3}, [%4];"
                 : "=r"(a0), "=r"(a1), "=r"(a2), "=r"(a3) : "r"(saddr));
}

// Store one fp32 chunk into smem as fp16, XOR swizzle on the COMPLETE byte
// offset: (m*256 + k*2) ^ ((m&7)<<4). Used only for the x chunk (slot 0).
__device__ __forceinline__ void st_chunk(const float4* v, char* zbuf, int tid) {
#pragma unroll
    for (int i = 0; i < 2; i++) {
        int f  = i * NTHREADS + tid;
        int m  = f >> 5;
        int k4 = (f & 31) * 4;
        unsigned off = (unsigned)(m * 256 + k4 * 2) ^ (((unsigned)m & 7u) << 4);
        __half2 h01 = __float22half2_rn(make_float2(v[i].x, v[i].y));
        __half2 h23 = __float22half2_rn(make_float2(v[i].z, v[i].w));
        uint2 pk;
        pk.x = *(unsigned*)&h01;
        pk.y = *(unsigned*)&h23;
        *(uint2*)(zbuf + off) = pk;
    }
}

__global__ void __launch_bounds__(NTHREADS, 1)
liquid_kernel(const float* __restrict__ x_seq,
              const float* __restrict__ Wc, const float* __restrict__ bc,
              const float* __restrict__ Wt, const float* __restrict__ bt,
              const float* __restrict__ Wo, const float* __restrict__ bo,
              float* __restrict__ out) {
    extern __shared__ unsigned smem[];
    unsigned* sWf  = smem + OFF_WF;
    char*     sZ   = (char*)(smem + OFF_Z);
    float*    sEpi = (float*)(smem + OFF_EPI);
    float*    sBc  = (float*)(smem + OFF_BC);
    float*    sBt  = (float*)(smem + OFF_BT);

    const int tid  = threadIdx.x;
    const int gb   = blockIdx.x / P_N;
    const int jn   = blockIdx.x % P_N;
    const int b0   = gb * B_TILE;
    const int n0   = jn * N_SLICE;
    const int lane = tid & 31;
    const int wid  = tid >> 5;           // 0..15
    const int wm   = wid & 1;            // M half (16 rows)
    const int wn   = (wid >> 1) & 1;     // N half (32 combined cols)
    const int wk   = wid >> 2;           // K quarter (2 kg16 per chunk)

    // ---- init: weights into B-fragment layout (fp16) in smem staging ----
    for (int e = tid; e < KGG_TOT * 4 * 32 * 4; e += NTHREADS) {
        int q    = e & 3;
        int l    = (e >> 2) & 31;
        int ntp  = (e >> 7) & 3;
        int kgg  = e >> 9;
        int nt   = 2 * ntp + (q >> 1);
        int k0   = kgg * 16 + (l & 3) * 2 + (q & 1) * 8;
        int cc   = nt * 8 + (l >> 2);
        const float* W = (cc < N_SLICE) ? (Wc + n0 + cc) : (Wt + n0 + cc - N_SLICE);
        float w0 = W[(size_t)k0 * HID];
        float w1 = W[(size_t)(k0 + 1) * HID];
        __half2 h = __float22half2_rn(make_float2(w0, w1));
        sWf[e] = *(unsigned*)&h;
    }
    if (tid < N_SLICE) { sBc[tid] = bc[n0 + tid]; sBt[tid] = bt[n0 + tid]; }
    const float wo_v = Wo[n0 + lane];
    const float bo_v = bo[0];
    __syncthreads();

    // ---- load this warp's B fragments into REGISTERS (persistent) ----
    // warp's kgg list: t = 0..9 -> kgg = (t>>1)*8 + wk*2 + (t&1)
    uint4 bf[10][2];
#pragma unroll
    for (int t = 0; t < 10; t++) {
        int kgg = (t >> 1) * NKG + wk * 2 + (t & 1);
#pragma unroll
        for (int tp = 0; tp < 2; tp++) {
            int ntp = wn * 2 + tp;
            bf[t][tp] = *(const uint4*)(sWf + ((kgg * 4 + ntp) * 32 + lane) * 4);
        }
    }

    // Per-thread staging coordinates for the x chunk (step-invariant)
    const int sm0 = tid >> 5;
    const int sk0 = (tid & 31) * 4;
    const int sm1 = (NTHREADS + tid) >> 5;

    // ldmatrix base offsets (kg-in-chunk = wk*2 + {0,1}); swizzle on the
    // complete low-13-bit offset; chunk slot adds bits 13+ (carry-free).
    const int arow = wm * 16 + ((lane >> 3) & 1) * 8 + (lane & 7);
    const int acol = ((lane >> 4) & 1) * 16;
    const unsigned zsh = (unsigned)__cvta_generic_to_shared(sZ);
    unsigned aoff[2];
#pragma unroll
    for (int i = 0; i < 2; i++) {
        int kg = wk * 2 + i;
        aoff[i] = zsh + (((unsigned)(arow * 256 + kg * 32 + acol)) ^
                         (((unsigned)arow & 7u) << 4));
    }

    // Epilogue h-store pointers (2 elements: b = wid and 16+wid, col = n0+lane)
    const int hcol = n0 + lane;
    char* const hz_w0 = &g_hz[0][gb][hcol >> 7]
        [((unsigned)((wid) * 256 + (hcol & 127) * 2)) ^ (((unsigned)wid & 7u) << 4)];
    char* const hz_w1 = &g_hz[0][gb][hcol >> 7]
        [((unsigned)((16 + wid) * 256 + (hcol & 127) * 2)) ^ (((unsigned)(16 + wid) & 7u) << 4)];
    const size_t hz_buf_stride = (size_t)P_B * 4 * ZBUF_BYTES;

    float h_loc[2] = {0.f, 0.f};

    // Prestage x chunk for step 0 into slot 0
    {
        float4 vx[2];
        const float* src = x_seq + (size_t)b0 * DIN;
        vx[0] = *(const float4*)(src + (size_t)sm0 * DIN + sk0);
        vx[1] = *(const float4*)(src + (size_t)sm1 * DIN + sk0);
        st_chunk(vx, sZ, tid);
    }
    __syncthreads();

    for (int s = 0; s < T_STEPS; s++) {
        const int p = s & 1;

        // ---- issue h LDGs (identity copy of pre-swizzled fp16) ----
        uint4 hv[4];
        if (s > 0) {
            const char* hb = &g_hz[p][gb][0][0];
#pragma unroll
            for (int c = 0; c < 4; c++)
                hv[c] = __ldcg((const uint4*)(hb + c * ZBUF_BYTES) + tid);
        } else {
            hv[0] = hv[1] = hv[2] = hv[3] = make_uint4(0u, 0u, 0u, 0u);
        }

        // ---- y reduce for previous step (warp 0, overlaps h LDG) ----
        if (s > 0 && tid < 32) {
            int r = tid >> 4, j = tid & 15;
            int b = b0 + jn * 2 + r;
            float v = __ldcg(&g_ypart[p ^ 1][b][j]);
#pragma unroll
            for (int o = 8; o; o >>= 1) v += __shfl_xor_sync(0xffffffffu, v, o);
            if (j == 0) out[(size_t)(s - 1) * BATCH + b] = v + bo_v;
        }

        // ---- chunk-0 MMA (x slot, staged last step) while h LDGs fly ----
        float acc[4][4] = {};
#pragma unroll
        for (int t = 0; t < 2; t++) {
            unsigned a0, a1, a2, a3;
            ldsm_x4(a0, a1, a2, a3, aoff[t]);
#pragma unroll
            for (int tp = 0; tp < 2; tp++) {
                mma_f16(acc[tp * 2 + 0], a0, a1, a2, a3, bf[t][tp].x, bf[t][tp].y);
                mma_f16(acc[tp * 2 + 1], a0, a1, a2, a3, bf[t][tp].z, bf[t][tp].w);
            }
        }

        // ---- stage h chunks into slots 1..4 ----
#pragma unroll
        for (int c = 0; c < 4; c++)
            *((uint4*)(sZ + (c + 1) * ZBUF_BYTES) + tid) = hv[c];
        __syncthreads();

        // ---- issue next step's x LDG (hidden under MMA) ----
        float4 vx[2];
        if (s + 1 < T_STEPS) {
            const float* src = x_seq + ((size_t)(s + 1) * BATCH + b0) * DIN;
            vx[0] = *(const float4*)(src + (size_t)sm0 * DIN + sk0);
            vx[1] = *(const float4*)(src + (size_t)sm1 * DIN + sk0);
        }

        // ---- chunks 1..4 MMA (B fragments already in registers) ----
#pragma unroll
        for (int t = 2; t < 10; t++) {
            unsigned c = (unsigned)(t >> 1);
            unsigned a0, a1, a2, a3;
            ldsm_x4(a0, a1, a2, a3, aoff[t & 1] + c * ZBUF_BYTES);
#pragma unroll
            for (int tp = 0; tp < 2; tp++) {
                mma_f16(acc[tp * 2 + 0], a0, a1, a2, a3, bf[t][tp].x, bf[t][tp].y);
                mma_f16(acc[tp * 2 + 1], a0, a1, a2, a3, bf[t][tp].z, bf[t][tp].w);
            }
        }

        // ---- scatter partial accumulators to per-wk epilogue buffers ----
        {
            float* eb = sEpi + wk * 2112;
            int row = wm * 16 + (lane >> 2);
#pragma unroll
            for (int t = 0; t < 4; t++) {
                int col = wn * 32 + t * 8 + (lane & 3) * 2;
                *(float2*)&eb[row * 66 + col]       = make_float2(acc[t][0], acc[t][1]);
                *(float2*)&eb[(row + 8) * 66 + col] = make_float2(acc[t][2], acc[t][3]);
            }
        }
        __syncthreads();

        // ---- epilogue: reduce, activations, h update, tau, y-partials ----
        char* hz_base0 = hz_w0 + (size_t)(p ^ 1) * hz_buf_stride;
        char* hz_base1 = hz_w1 + (size_t)(p ^ 1) * hz_buf_stride;
#pragma unroll
        for (int i = 0; i < 2; i++) {
            int b  = i * 16 + wid;      // local batch row
            int nl = lane;
            float uc = sBc[nl], ut = sBt[nl];
#pragma unroll
            for (int q = 0; q < 4; q++) {
                uc += sEpi[q * 2112 + b * 66 + nl];
                ut += sEpi[q * 2112 + b * 66 + nl + 32];
            }
            float ea   = __expf(-2.f * fabsf(uc));
            float cand = copysignf(__fdividef(1.f - ea, 1.f + ea), uc);
            float sg   = __fdividef(1.f, 1.f + __expf(-ut));
            float tau  = 0.2f + 1.8f * sg;
            float h    = h_loc[i];
            float hn   = h + 0.1f * __fdividef(cand - h, tau);
            h_loc[i]   = hn;
            *(__half*)(i == 0 ? hz_base0 : hz_base1) = __float2half_rn(hn);
            __stcs(&out[(size_t)T_STEPS * BATCH +
                        ((size_t)s * BATCH + b0 + b) * HID + n0 + nl], tau);

            float pp = hn * wo_v;
#pragma unroll
            for (int o = 16; o; o >>= 1) pp += __shfl_xor_sync(0xffffffffu, pp, o);
            if (lane == 0) g_ypart[s & 1][b0 + b][jn] = pp;
        }

        // ---- prestage next x into slot 0 (all slot-0 reads done this step) ----
        if (s + 1 < T_STEPS) st_chunk(vx, sZ, tid);

        // ---- flat barrier: release own flag, poll all 16 (one L2 RTT) ----
        __syncthreads();
        if (tid == 0) {
            asm volatile("st.release.gpu.global.u32 [%0], %1;"
                         :: "l"(&g_flag[gb][jn]), "r"((unsigned)(s + 1)) : "memory");
        }
        if (tid < P_N) {
            const unsigned* fp = &g_flag[gb][tid];
            unsigned v;
            do {
                asm volatile("ld.acquire.gpu.global.u32 %0, [%1];"
                             : "=r"(v) : "l"(fp) : "memory");
            } while (v < (unsigned)(s + 1));
        }
        __syncthreads();
    }

    // ---- y for the final step ----
    if (tid < 32) {
        int r = tid >> 4, j = tid & 15;
        int b = b0 + jn * 2 + r;
        float v = __ldcg(&g_ypart[(T_STEPS & 1) ^ 1][b][j]);
#pragma unroll
        for (int o = 8; o; o >>= 1) v += __shfl_xor_sync(0xffffffffu, v, o);
        if (j == 0) out[(size_t)(T_STEPS - 1) * BATCH + b] = v + bo_v;
    }

    // ---- reset flags for the next graph replay (last CTA of each group) ----
    if (tid == 0) {
        unsigned old;
        asm volatile("atom.add.release.gpu.global.u32 %0, [%1], %2;"
                     : "=r"(old) : "l"(&g_exit[gb]), "r"(1u) : "memory");
        if (old == P_N - 1u) {
            for (int j = 0; j < P_N; j++) g_flag[gb][j] = 0u;
            g_exit[gb] = 0u;
        }
    }
}

extern "C" void kernel_launch(void* const* d_in, const int* in_sizes, int n_in,
                              void* d_out, int out_size) {
    (void)in_sizes; (void)n_in; (void)out_size;
    const float* x_seq = (const float*)d_in[0];
    const float* Wc    = (const float*)d_in[1];
    const float* bc    = (const float*)d_in[2];
    const float* Wt    = (const float*)d_in[3];
    const float* bt    = (const float*)d_in[4];
    const float* Wo    = (const float*)d_in[5];
    const float* bo    = (const float*)d_in[6];
    float* out = (float*)d_out;

    cudaFuncSetAttribute(liquid_kernel, cudaFuncAttributeMaxDynamicSharedMemorySize, SMEM_BYTES);
    liquid_kernel<<<GRID, NTHREADS, SMEM_BYTES>>>(x_seq, Wc, bc, Wt, bt, Wo, bo, out);
}

// round 8
// speedup vs baseline: 1.1787x; 1.1787x over previous
#include <cuda_runtime.h>
#include <cuda_fp16.h>
#include <cstdint>

// Problem constants
#define T_STEPS 512
#define BATCH   256
#define DIN     128
#define HID     512
#define KTOT    640          // DIN + HID

// Tiling
#define P_B 8                // batch groups
#define P_N 16               // n-slices per group
#define B_TILE 32            // batch rows per CTA (M)
#define N_SLICE 32           // H columns per CTA
#define KC 128               // K chunk (halves) per z slot
#define NCHUNK 5             // 640 / 128
#define NKG 8                // kg16 groups per chunk
#define KGG_TOT 40           // 640 / 16
#define NTHREADS 512
#define GRID (P_B * P_N)

// Shared memory layout (uint32 units)
#define OFF_WF  0            // B frag staging: 40 kg * 4 ntp * 32 lane * 4 = 20480 u32 (80KB)
#define OFF_Z   20480        // 5 chunk slots * 2048 u32 (each 32 rows x 128 halves = 8KB)
#define OFF_EPI 30720        // 4 wk-buffers * 32*66 = 8448
#define OFF_BC  39168        // 32
#define OFF_BT  39200        // 32
#define SMEM_U32 39232
#define SMEM_BYTES (SMEM_U32 * 4)   // 156928 B

#define ZBUF_BYTES 8192

// Persistent device state.
// g_hz: hidden state as fp16, PRE-SWIZZLED in the smem fragment byte layout.
__device__ __align__(16) char g_hz[2][P_B][4][ZBUF_BYTES];
__device__ float    g_ypart[2][BATCH][P_N];
__device__ unsigned g_count[P_B];             // barrier counters (zero-init)
__device__ unsigned g_sense[P_B];             // sense (512 toggles/launch -> back to 0)

__device__ __forceinline__ void mma_f16(float* c, unsigned a0, unsigned a1,
                                        unsigned a2, unsigned a3,
                                        unsigned b0, unsigned b1) {
    asm("mma.sync.aligned.m16n8k16.row.col.f32.f16.f16.f32 "
        "{%0,%1,%2,%3},{%4,%5,%6,%7},{%8,%9},{%0,%1,%2,%3};"
        : "+f"(c[0]), "+f"(c[1]), "+f"(c[2]), "+f"(c[3])
        : "r"(a0), "r"(a1), "r"(a2), "r"(a3), "r"(b0), "r"(b1));
}

__device__ __forceinline__ void ldsm_x4(unsigned& a0, unsigned& a1,
                                        unsigned& a2, unsigned& a3, unsigned saddr) {
    asm volatile("ldmatrix.sync.aligned.m8n8.x4.shared.b16 {%0,%1,%2,%3}, [%4];"
                 : "=r"(a0), "=r"(a1), "=r"(a2), "=r"(a3) : "r"(saddr));
}

// Store one fp32 chunk into smem as fp16, XOR swizzle on the COMPLETE byte
// offset: (m*256 + k*2) ^ ((m&7)<<4). Used only for the x chunk (slot 0).
__device__ __forceinline__ void st_chunk(const float4* v, char* zbuf, int tid) {
#pragma unroll
    for (int i = 0; i < 2; i++) {
        int f  = i * NTHREADS + tid;
        int m  = f >> 5;
        int k4 = (f & 31) * 4;
        unsigned off = (unsigned)(m * 256 + k4 * 2) ^ (((unsigned)m & 7u) << 4);
        __half2 h01 = __float22half2_rn(make_float2(v[i].x, v[i].y));
        __half2 h23 = __float22half2_rn(make_float2(v[i].z, v[i].w));
        uint2 pk;
        pk.x = *(unsigned*)&h01;
        pk.y = *(unsigned*)&h23;
        *(uint2*)(zbuf + off) = pk;
    }
}

__global__ void __launch_bounds__(NTHREADS, 1)
liquid_kernel(const float* __restrict__ x_seq,
              const float* __restrict__ Wc, const float* __restrict__ bc,
              const float* __restrict__ Wt, const float* __restrict__ bt,
              const float* __restrict__ Wo, const float* __restrict__ bo,
              float* __restrict__ out) {
    extern __shared__ unsigned smem[];
    unsigned* sWf  = smem + OFF_WF;
    char*     sZ   = (char*)(smem + OFF_Z);
    float*    sEpi = (float*)(smem + OFF_EPI);
    float*    sBc  = (float*)(smem + OFF_BC);
    float*    sBt  = (float*)(smem + OFF_BT);

    const int tid  = threadIdx.x;
    const int gb   = blockIdx.x / P_N;
    const int jn   = blockIdx.x % P_N;
    const int b0   = gb * B_TILE;
    const int n0   = jn * N_SLICE;
    const int lane = tid & 31;
    const int wid  = tid >> 5;           // 0..15
    const int wm   = wid & 1;            // M half (16 rows)
    const int wn   = (wid >> 1) & 1;     // N half (32 combined cols)
    const int wk   = wid >> 2;           // K quarter (2 kg16 per chunk)

    // ---- init: weights into B-fragment layout (fp16) in smem staging ----
    for (int e = tid; e < KGG_TOT * 4 * 32 * 4; e += NTHREADS) {
        int q    = e & 3;
        int l    = (e >> 2) & 31;
        int ntp  = (e >> 7) & 3;
        int kgg  = e >> 9;
        int nt   = 2 * ntp + (q >> 1);
        int k0   = kgg * 16 + (l & 3) * 2 + (q & 1) * 8;
        int cc   = nt * 8 + (l >> 2);
        const float* W = (cc < N_SLICE) ? (Wc + n0 + cc) : (Wt + n0 + cc - N_SLICE);
        float w0 = W[(size_t)k0 * HID];
        float w1 = W[(size_t)(k0 + 1) * HID];
        __half2 h = __float22half2_rn(make_float2(w0, w1));
        sWf[e] = *(unsigned*)&h;
    }
    if (tid < N_SLICE) { sBc[tid] = bc[n0 + tid]; sBt[tid] = bt[n0 + tid]; }
    const float wo_v = Wo[n0 + lane];
    const float bo_v = bo[0];
    __syncthreads();

    // ---- this warp's B fragments -> REGISTERS (persistent, step-invariant) ----
    // t = 0..9 -> kgg = (t>>1)*8 + wk*2 + (t&1); chunk = t>>1, kg-in-chunk parity = t&1
    uint4 bf[10][2];
#pragma unroll
    for (int t = 0; t < 10; t++) {
        int kgg = (t >> 1) * NKG + wk * 2 + (t & 1);
#pragma unroll
        for (int tp = 0; tp < 2; tp++) {
            int ntp = wn * 2 + tp;
            bf[t][tp] = *(const uint4*)(sWf + ((kgg * 4 + ntp) * 32 + lane) * 4);
        }
    }

    // Per-thread staging coordinates for the x chunk (step-invariant)
    const int sm0 = tid >> 5;
    const int sk0 = (tid & 31) * 4;
    const int sm1 = (NTHREADS + tid) >> 5;

    // ldmatrix base offsets (kg-in-chunk = wk*2 + {0,1}); swizzle on the
    // complete low-13-bit offset; chunk slot adds bits 13+ (carry-free).
    const int arow = wm * 16 + ((lane >> 3) & 1) * 8 + (lane & 7);
    const int acol = ((lane >> 4) & 1) * 16;
    const unsigned zsh = (unsigned)__cvta_generic_to_shared(sZ);
    unsigned aoff[2];
#pragma unroll
    for (int i = 0; i < 2; i++) {
        int kg = wk * 2 + i;
        aoff[i] = zsh + (((unsigned)(arow * 256 + kg * 32 + acol)) ^
                         (((unsigned)arow & 7u) << 4));
    }

    // Epilogue h-store pointers (2 elements: b = wid and 16+wid, col = n0+lane)
    const int hcol = n0 + lane;
    char* const hz_w0 = &g_hz[0][gb][hcol >> 7]
        [((unsigned)((wid) * 256 + (hcol & 127) * 2)) ^ (((unsigned)wid & 7u) << 4)];
    char* const hz_w1 = &g_hz[0][gb][hcol >> 7]
        [((unsigned)((16 + wid) * 256 + (hcol & 127) * 2)) ^ (((unsigned)(16 + wid) & 7u) << 4)];
    const size_t hz_buf_stride = (size_t)P_B * 4 * ZBUF_BYTES;

    float h_loc[2] = {0.f, 0.f};

    // Prestage x chunk for step 0 into slot 0
    {
        float4 vx[2];
        const float* src = x_seq + (size_t)b0 * DIN;
        vx[0] = *(const float4*)(src + (size_t)sm0 * DIN + sk0);
        vx[1] = *(const float4*)(src + (size_t)sm1 * DIN + sk0);
        st_chunk(vx, sZ, tid);
    }
    __syncthreads();

    unsigned lsense = 0;

    for (int s = 0; s < T_STEPS; s++) {
        const int p = s & 1;

        // ---- stage h chunks 1..4 (identity copy of pre-swizzled fp16) ----
        {
            uint4 hv[4];
            if (s > 0) {
                const char* hb = &g_hz[p][gb][0][0];
#pragma unroll
                for (int c = 0; c < 4; c++)
                    hv[c] = __ldcg((const uint4*)(hb + c * ZBUF_BYTES) + tid);
            } else {
                hv[0] = hv[1] = hv[2] = hv[3] = make_uint4(0u, 0u, 0u, 0u);
            }
#pragma unroll
            for (int c = 0; c < 4; c++)
                *((uint4*)(sZ + (c + 1) * ZBUF_BYTES) + tid) = hv[c];
        }

        // ---- finish y for previous step (warp 0, overlaps staging) ----
        if (s > 0 && tid < 32) {
            int r = tid >> 4, j = tid & 15;
            int b = b0 + jn * 2 + r;
            float v = __ldcg(&g_ypart[p ^ 1][b][j]);
#pragma unroll
            for (int o = 8; o; o >>= 1) v += __shfl_xor_sync(0xffffffffu, v, o);
            if (j == 0) out[(size_t)(s - 1) * BATCH + b] = v + bo_v;
        }
        __syncthreads();

        // ---- GEMM: all 5 chunks, B fragments from registers ----
        float acc[4][4] = {};
#pragma unroll
        for (int t = 0; t < 10; t++) {
            unsigned c = (unsigned)(t >> 1);
            unsigned a0, a1, a2, a3;
            ldsm_x4(a0, a1, a2, a3, aoff[t & 1] + c * ZBUF_BYTES);
#pragma unroll
            for (int tp = 0; tp < 2; tp++) {
                mma_f16(acc[tp * 2 + 0], a0, a1, a2, a3, bf[t][tp].x, bf[t][tp].y);
                mma_f16(acc[tp * 2 + 1], a0, a1, a2, a3, bf[t][tp].z, bf[t][tp].w);
            }
        }

        // ---- scatter partial accumulators to per-wk epilogue buffers ----
        {
            float* eb = sEpi + wk * 2112;
            int row = wm * 16 + (lane >> 2);
#pragma unroll
            for (int t = 0; t < 4; t++) {
                int col = wn * 32 + t * 8 + (lane & 3) * 2;
                *(float2*)&eb[row * 66 + col]       = make_float2(acc[t][0], acc[t][1]);
                *(float2*)&eb[(row + 8) * 66 + col] = make_float2(acc[t][2], acc[t][3]);
            }
        }

        // ---- issue next step's x LDG (lands during epilogue/barrier) ----
        float4 vx[2];
        if (s + 1 < T_STEPS) {
            const float* src = x_seq + ((size_t)(s + 1) * BATCH + b0) * DIN;
            vx[0] = *(const float4*)(src + (size_t)sm0 * DIN + sk0);
            vx[1] = *(const float4*)(src + (size_t)sm1 * DIN + sk0);
        }
        __syncthreads();

        // ---- epilogue: reduce wk partials, activations, h update ----
        float tau_sv[2];
        char* hz_base0 = hz_w0 + (size_t)(p ^ 1) * hz_buf_stride;
        char* hz_base1 = hz_w1 + (size_t)(p ^ 1) * hz_buf_stride;
#pragma unroll
        for (int i = 0; i < 2; i++) {
            int b  = i * 16 + wid;      // local batch row
            int nl = lane;
            float uc = sBc[nl], ut = sBt[nl];
#pragma unroll
            for (int q = 0; q < 4; q++) {
                uc += sEpi[q * 2112 + b * 66 + nl];
                ut += sEpi[q * 2112 + b * 66 + nl + 32];
            }
            float ea   = __expf(-2.f * fabsf(uc));
            float cand = copysignf(__fdividef(1.f - ea, 1.f + ea), uc);
            float sg   = __fdividef(1.f, 1.f + __expf(-ut));
            float tau  = 0.2f + 1.8f * sg;
            tau_sv[i]  = tau;
            float h    = h_loc[i];
            float hn   = h + 0.1f * __fdividef(cand - h, tau);
            h_loc[i]   = hn;
            *(__half*)(i == 0 ? hz_base0 : hz_base1) = __float2half_rn(hn);

            float pp = hn * wo_v;
#pragma unroll
            for (int o = 16; o; o >>= 1) pp += __shfl_xor_sync(0xffffffffu, pp, o);
            if (lane == 0) g_ypart[s & 1][b0 + b][jn] = pp;
        }

        // ---- barrier arrive; overlap tau stores + x staging with the spin ----
        __syncthreads();
        if (tid == 0) {
            lsense ^= 1u;
            unsigned old;
            asm volatile("atom.add.release.gpu.global.u32 %0, [%1], %2;"
                         : "=r"(old) : "l"(&g_count[gb]), "r"(1u) : "memory");
            if (old == P_N - 1u) {
                g_count[gb] = 0u;
                asm volatile("st.release.gpu.global.u32 [%0], %1;"
                             :: "l"(&g_sense[gb]), "r"(lsense) : "memory");
            } else {
                unsigned v;
                do {
                    asm volatile("ld.acquire.gpu.global.u32 %0, [%1];"
                                 : "=r"(v) : "l"(&g_sense[gb]) : "memory");
                } while (v != lsense);
            }
        }
        // tau is never read cross-CTA: store outside the ordered region.
#pragma unroll
        for (int i = 0; i < 2; i++) {
            int b = i * 16 + wid;
            __stcs(&out[(size_t)T_STEPS * BATCH +
                        ((size_t)s * BATCH + b0 + b) * HID + n0 + lane], tau_sv[i]);
        }
        if (s + 1 < T_STEPS) st_chunk(vx, sZ, tid);   // slot 0: next x
        __syncthreads();
    }

    // ---- y for the final step ----
    if (tid < 32) {
        int r = tid >> 4, j = tid & 15;
        int b = b0 + jn * 2 + r;
        float v = __ldcg(&g_ypart[(T_STEPS & 1) ^ 1][b][j]);
#pragma unroll
        for (int o = 8; o; o >>= 1) v += __shfl_xor_sync(0xffffffffu, v, o);
        if (j == 0) out[(size_t)(T_STEPS - 1) * BATCH + b] = v + bo_v;
    }
}

extern "C" void kernel_launch(void* const* d_in, const int* in_sizes, int n_in,
                              void* d_out, int out_size) {
    (void)in_sizes; (void)n_in; (void)out_size;
    const float* x_seq = (const float*)d_in[0];
    const float* Wc    = (const float*)d_in[1];
    const float* bc    = (const float*)d_in[2];
    const float* Wt    = (const float*)d_in[3];
    const float* bt    = (const float*)d_in[4];
    const float* Wo    = (const float*)d_in[5];
    const float* bo    = (const float*)d_in[6];
    float* out = (float*)d_out;

    cudaFuncSetAttribute(liquid_kernel, cudaFuncAttributeMaxDynamicSharedMemorySize, SMEM_BYTES);
    liquid_kernel<<<GRID, NTHREADS, SMEM_BYTES>>>(x_seq, Wc, bc, Wt, bt, Wo, bo, out);
}